// round 8
// baseline (speedup 1.0000x reference)
#include <cuda_runtime.h>
#include <cstddef>

#define NF 32
#define NU 256
#define INV_U 0.00390625f
#define PSPLIT 32

typedef unsigned long long u64;

// ---- device scratch (no runtime allocation allowed) ----
__device__ float g_pcp[NF * PSPLIT * NU];   // prep partials
__device__ float g_pcn[NF * PSPLIT * NU];
// fused fast-path params: [f][slot][NU], slot0=0.5*Cpos, slot1=0.5*Cneg, slot2=0.5*Wg
__device__ float g_P  [NF * 3 * NU];
__device__ float g_b2h[NF * NU];            // 0.5 * b2   (general path)
__device__ float g_bg2[NF * NU];            // 0.5 * bg   (general path)
__device__ float g_gmean[NF];
__device__ float g_bmean[NF];
__device__ float g_wf[NF];                  // sigmoid(bs) for fast path
__device__ int   g_fb1[NF];                 // b1 row == 0
__device__ int   g_flag[NF];                // b1==0 && b2==0 && bg==0 && gamma==1 && beta==0

// ---- f32x2 packed math (Blackwell FFMA2 path) ----
__device__ __forceinline__ u64 pk(float lo, float hi) {
    u64 r; asm("mov.b64 %0,{%1,%2};" : "=l"(r) : "f"(lo), "f"(hi)); return r;
}
__device__ __forceinline__ void upk(u64 v, float& lo, float& hi) {
    asm("mov.b64 {%0,%1},%2;" : "=f"(lo), "=f"(hi) : "l"(v));
}
__device__ __forceinline__ u64 fma2(u64 a, u64 b, u64 c) {
    u64 d; asm("fma.rn.f32x2 %0,%1,%2,%3;" : "=l"(d) : "l"(a), "l"(b), "l"(c)); return d;
}
__device__ __forceinline__ u64 add2(u64 a, u64 b) {
    u64 d; asm("add.rn.f32x2 %0,%1,%2;" : "=l"(d) : "l"(a), "l"(b)); return d;
}
__device__ __forceinline__ u64 mul2(u64 a, u64 b) {
    u64 d; asm("mul.rn.f32x2 %0,%1,%2;" : "=l"(d) : "l"(a), "l"(b)); return d;
}
__device__ __forceinline__ float tanh_a(float z) {
    float r; asm("tanh.approx.f32 %0,%1;" : "=f"(r) : "f"(z)); return r;
}
__device__ __forceinline__ float rsqf_(float d) {
    float r; asm("rsqrt.approx.f32 %0,%1;" : "=f"(r) : "f"(d)); return r;
}
__device__ __forceinline__ u64 shfl64x(u64 v, int m) {
    return __shfl_xor_sync(0xffffffffu, v, m);
}
// sigmoid(z) = 0.5*tanh(0.5*z) + 0.5   (zh = 0.5*z already)
__device__ __forceinline__ float sig_h(float zh) { return fmaf(0.5f, tanh_a(zh), 0.5f); }

#define LD4U(dst, src) do { \
    ulonglong2 _a = *(const ulonglong2*)((src)); \
    ulonglong2 _b = *(const ulonglong2*)((src) + 4); \
    (dst)[0]=_a.x; (dst)[1]=_a.y; (dst)[2]=_b.x; (dst)[3]=_b.y; } while (0)

// ============================================================
// Prep stage 1: partial ReLU-collapsed dense2 reduction.
// grid (NF, PSPLIT=32) x 64 threads. All 8 row-loads are
// explicitly buffered BEFORE the FMA loop to force MLP=8
// (R7's 32-reg allocation serialized them).
// ============================================================
__global__ void prep1_kernel(
    const float* __restrict__ W1, const float* __restrict__ W2)
{
    const int f = blockIdx.x;
    const int s = blockIdx.y;
    const int q = threadIdx.x;          // column quad: cols [4q, 4q+4)

    const float4 w1a = *(const float4*)(W1 + f * NU + s * 8);
    const float4 w1b = *(const float4*)(W1 + f * NU + s * 8 + 4);
    const float w1[8] = {w1a.x, w1a.y, w1a.z, w1a.w, w1b.x, w1b.y, w1b.z, w1b.w};

    const float* base = W2 + (size_t)f * NU * NU + (size_t)(s * 8) * NU + q * 4;
    float4 buf[8];
    #pragma unroll
    for (int i = 0; i < 8; ++i)
        buf[i] = *(const float4*)(base + (size_t)i * NU);

    float4 cp = make_float4(0.f, 0.f, 0.f, 0.f);
    float4 cn = make_float4(0.f, 0.f, 0.f, 0.f);
    #pragma unroll
    for (int i = 0; i < 8; ++i) {
        const float wp = fmaxf(w1[i], 0.0f), wn = fminf(w1[i], 0.0f);
        cp.x = fmaf(wp, buf[i].x, cp.x); cp.y = fmaf(wp, buf[i].y, cp.y);
        cp.z = fmaf(wp, buf[i].z, cp.z); cp.w = fmaf(wp, buf[i].w, cp.w);
        cn.x = fmaf(wn, buf[i].x, cn.x); cn.y = fmaf(wn, buf[i].y, cn.y);
        cn.z = fmaf(wn, buf[i].z, cn.z); cn.w = fmaf(wn, buf[i].w, cn.w);
    }
    *(float4*)(g_pcp + (f * PSPLIT + s) * NU + q * 4) = cp;
    *(float4*)(g_pcn + (f * PSPLIT + s) * NU + q * 4) = cn;
}

// ============================================================
// Prep stage 2: deterministic partial reduce + fused param
// block + gamma/beta means + flags + fast-path weights.
// ============================================================
__global__ void __launch_bounds__(256) prep2_kernel(
    const float* __restrict__ b1, const float* __restrict__ b2,
    const float* __restrict__ Wg, const float* __restrict__ bg,
    const float* __restrict__ gamma, const float* __restrict__ beta,
    const float* __restrict__ bs)
{
    const int f = blockIdx.x;
    const int v = threadIdx.x;

    __shared__ float red[NU];
    __shared__ int fl_b1, fl_all;
    if (v == 0) { fl_b1 = 1; fl_all = 1; }
    __syncthreads();
    // all writers store 0: race-free
    if (b1[f * NU + v] != 0.0f) { fl_b1 = 0; fl_all = 0; }
    if (b2[f * NU + v] != 0.0f) fl_all = 0;
    if (bg[f * NU + v] != 0.0f) fl_all = 0;
    if (gamma[f * NU + v] != 1.0f) fl_all = 0;
    if (beta[f * NU + v]  != 0.0f) fl_all = 0;

    float cp = 0.0f, cn = 0.0f;
    #pragma unroll 8
    for (int s = 0; s < PSPLIT; ++s) {
        cp += g_pcp[(f * PSPLIT + s) * NU + v];
        cn += g_pcn[(f * PSPLIT + s) * NU + v];
    }
    g_P[f * 3 * NU + v]          = 0.5f * cp;     // slot 0: 0.5*Cpos
    g_P[f * 3 * NU + NU + v]     = 0.5f * cn;     // slot 1: 0.5*Cneg
    g_P[f * 3 * NU + 2 * NU + v] = 0.5f * Wg[f * NU + v];  // slot 2
    g_b2h[f * NU + v] = 0.5f * b2[f * NU + v];
    g_bg2[f * NU + v] = 0.5f * bg[f * NU + v];

    red[v] = gamma[f * NU + v]; __syncthreads();
    for (int s = 128; s > 0; s >>= 1) { if (v < s) red[v] += red[v + s]; __syncthreads(); }
    if (v == 0) g_gmean[f] = red[0] * INV_U;
    __syncthreads();
    red[v] = beta[f * NU + v]; __syncthreads();
    for (int s = 128; s > 0; s >>= 1) { if (v < s) red[v] += red[v + s]; __syncthreads(); }
    if (v == 0) {
        g_bmean[f] = red[0] * INV_U;
        g_fb1[f]  = fl_b1;
        g_flag[f] = fl_all;
        g_wf[f]   = sig_h(0.5f * bs[f]);
    }
}

// Honest O(U) fallback when b1[f,:] is not all-zero (never taken on bench data).
// Produces t[j] = 0.5 * h2[j].
__device__ __noinline__ void slow_t(float xf, int f, int ubase,
                                    const float* __restrict__ W1, const float* __restrict__ b1,
                                    const float* __restrict__ W2, const float* __restrict__ b2,
                                    float* t)
{
    float h2v[8];
    #pragma unroll
    for (int j = 0; j < 8; ++j) h2v[j] = b2[f * NU + ubase + j];
    const float* w1r = W1 + f * NU;
    const float* b1r = b1 + f * NU;
    const float* w2r = W2 + (size_t)f * NU * NU + ubase;
    for (int k = 0; k < NU; ++k) {
        float h1 = fmaxf(fmaf(xf, w1r[k], b1r[k]), 0.0f);
        const float* w2k = w2r + (size_t)k * NU;
        #pragma unroll
        for (int j = 0; j < 8; ++j) h2v[j] = fmaf(h1, w2k[j], h2v[j]);
    }
    #pragma unroll
    for (int j = 0; j < 8; ++j) t[j] = 0.5f * h2v[j];
}

// ============================================================
// GENERAL two-pass path (correctness fallback; never taken on
// bench data). __noinline__ so its register pressure spills
// privately instead of taxing the fast path's allocation.
// Handles 2 samples (base, base+1) for this warp.
// ============================================================
__device__ __noinline__ void general_path(
    const float* __restrict__ x, const float* __restrict__ b2,
    const float* __restrict__ gamma, const float* __restrict__ beta,
    const float* __restrict__ W1, const float* __restrict__ b1,
    const float* __restrict__ W2,
    const float* __restrict__ Ws, const float* __restrict__ bs,
    float* __restrict__ out, int base, int lane)
{
    const unsigned FULL = 0xffffffffu;
    const int ub = lane * 8;

    float xr[2];
    #pragma unroll
    for (int s = 0; s < 2; ++s) xr[s] = x[(base + s) * NF + lane];

    float mlv[2] = {0,0}, muv[2] = {0,0}, ivv[2] = {0,0};

    #pragma unroll 1
    for (int f = 0; f < NF; ++f) {
        u64 cp2[4], cn2[4], wg2[4], bg2[4], b2h2[4], gm2[4];
        const float* pb = g_P + f * 3 * NU + ub;
        LD4U(cp2, pb);
        LD4U(cn2, pb + NU);
        LD4U(wg2, pb + 2 * NU);
        LD4U(bg2,  g_bg2 + f * NU + ub);
        LD4U(b2h2, g_b2h + f * NU + ub);
        LD4U(gm2,  gamma + f * NU + ub);
        const int fb1 = g_fb1[f];
        const float gmean = g_gmean[f], bmean = g_bmean[f];

        float s1[2], s2[2], s3[2];

        #pragma unroll
        for (int s = 0; s < 2; ++s) {
            const float xf = __shfl_sync(FULL, xr[s], f);
            const u64 xf2 = pk(xf, xf);
            const bool up = (xf > 0.0f);
            u64 t2[4];
            if (fb1) {
                #pragma unroll
                for (int jp = 0; jp < 4; ++jp) {
                    u64 c2 = up ? cp2[jp] : cn2[jp];
                    t2[jp] = fma2(xf2, c2, b2h2[jp]);
                }
            } else {
                float t[8];
                slow_t(xf, f, ub, W1, b1, W2, b2, t);
                #pragma unroll
                for (int jp = 0; jp < 4; ++jp) t2[jp] = pk(t[2*jp], t[2*jp+1]);
            }

            u64 a1 = 0ull, a2 = 0ull, a3 = 0ull;
            #pragma unroll
            for (int jp = 0; jp < 4; ++jp) {
                u64 z2 = fma2(xf2, wg2[jp], bg2[jp]);
                float zl, zh; upk(z2, zl, zh);
                u64 th2 = pk(tanh_a(zl), tanh_a(zh));
                u64 r2 = add2(fma2(t2[jp], th2, t2[jp]), xf2);
                a1 = add2(a1, r2);
                a2 = fma2(r2, r2, a2);
                a3 = fma2(gm2[jp], r2, a3);
            }
            float l, h;
            upk(a1, l, h); s1[s] = l + h;
            upk(a2, l, h); s2[s] = l + h;
            upk(a3, l, h); s3[s] = l + h;
        }
        #pragma unroll
        for (int m = 16; m > 0; m >>= 1) {
            #pragma unroll
            for (int s = 0; s < 2; ++s) {
                s1[s] += __shfl_xor_sync(FULL, s1[s], m);
                s2[s] += __shfl_xor_sync(FULL, s2[s], m);
                s3[s] += __shfl_xor_sync(FULL, s3[s], m);
            }
        }
        #pragma unroll
        for (int s = 0; s < 2; ++s) {
            float mu  = s1[s] * INV_U;
            float var = fmaf(s2[s], INV_U, -mu * mu);
            float iv  = rsqf_(var + 1e-3f);
            float t   = fmaf(-mu, gmean, s3[s] * INV_U);
            float ml  = fmaf(t, iv, bmean);
            bool mine = (lane == f);
            mlv[s] = mine ? ml : mlv[s];
            muv[s] = mine ? mu : muv[s];
            ivv[s] = mine ? iv : ivv[s];
        }
    }

    // selection weights: w[f'=lane] = sigmoid(ml . Ws[:,lane] + bs[lane])
    float wv[2];
    const float bsv = bs[lane];
    #pragma unroll
    for (int s = 0; s < 2; ++s) {
        float z = bsv;
        #pragma unroll
        for (int k = 0; k < NF; ++k)
            z = fmaf(__shfl_sync(FULL, mlv[s], k), Ws[k * NF + lane], z);
        wv[s] = sig_h(0.5f * z);
    }

    u64 o2[8];
    #pragma unroll
    for (int i = 0; i < 8; ++i) o2[i] = 0ull;

    // second pass: recompute r, apply LN affine, accumulate output
    #pragma unroll 1
    for (int f = 0; f < NF; ++f) {
        u64 cp2[4], cn2[4], wg2[4], bg2[4], b2h2[4], gm2[4], bt2[4];
        const float* pb = g_P + f * 3 * NU + ub;
        LD4U(cp2, pb);
        LD4U(cn2, pb + NU);
        LD4U(wg2, pb + 2 * NU);
        LD4U(bg2,  g_bg2 + f * NU + ub);
        LD4U(b2h2, g_b2h + f * NU + ub);
        LD4U(gm2,  gamma + f * NU + ub);
        LD4U(bt2,  beta  + f * NU + ub);
        const int fb1 = g_fb1[f];

        #pragma unroll
        for (int s = 0; s < 2; ++s) {
            const float xf = __shfl_sync(FULL, xr[s],  f);
            const float wq = __shfl_sync(FULL, wv[s],  f);
            const float mu = __shfl_sync(FULL, muv[s], f);
            const float iv = __shfl_sync(FULL, ivv[s], f);
            const float p  = wq * iv;
            const u64 xf2  = pk(xf, xf);
            const u64 p2   = pk(p, p);
            const u64 nmu2 = pk(-mu, -mu);
            const u64 wq2  = pk(wq, wq);
            const bool up = (xf > 0.0f);

            u64 t2[4];
            if (fb1) {
                #pragma unroll
                for (int jp = 0; jp < 4; ++jp) {
                    u64 c2 = up ? cp2[jp] : cn2[jp];
                    t2[jp] = fma2(xf2, c2, b2h2[jp]);
                }
            } else {
                float t[8];
                slow_t(xf, f, ub, W1, b1, W2, b2, t);
                #pragma unroll
                for (int jp = 0; jp < 4; ++jp) t2[jp] = pk(t[2*jp], t[2*jp+1]);
            }

            #pragma unroll
            for (int jp = 0; jp < 4; ++jp) {
                u64 z2 = fma2(xf2, wg2[jp], bg2[jp]);
                float zl, zh; upk(z2, zl, zh);
                u64 th2 = pk(tanh_a(zl), tanh_a(zh));
                u64 r2 = add2(fma2(t2[jp], th2, t2[jp]), xf2);
                u64 d2 = mul2(add2(r2, nmu2), gm2[jp]);
                o2[s*4+jp] = fma2(d2, p2, o2[s*4+jp]);
                o2[s*4+jp] = fma2(bt2[jp], wq2, o2[s*4+jp]);
            }
        }
    }

    #pragma unroll
    for (int s = 0; s < 2; ++s) {
        ulonglong2 v0, v1;
        v0.x = o2[s*4+0]; v0.y = o2[s*4+1];
        v1.x = o2[s*4+2]; v1.y = o2[s*4+3];
        ulonglong2* op = (ulonglong2*)(out + (size_t)(base + s) * NU + ub);
        op[0] = v0;
        op[1] = v1;
    }
}

// ============================================================
// Main fused kernel. 128-thread CTAs, 2 samples per warp ->
// grid 1024, __launch_bounds__(128,7) -> 28 warps/SM, single
// wave. Fast path: single pass on v = g*h2 (shift-invariant
// LN), predicated Cpos/Cneg select (ALU pipe), fused param
// block (one address register).
// ============================================================
__global__ void __launch_bounds__(128, 7) main_kernel(
    const float* __restrict__ x, const float* __restrict__ b2,
    const float* __restrict__ gamma, const float* __restrict__ beta,
    const float* __restrict__ W1, const float* __restrict__ b1,
    const float* __restrict__ W2,
    const float* __restrict__ Ws, const float* __restrict__ bs,
    float* __restrict__ out)
{
    const int lane = threadIdx.x & 31;
    const int warp = threadIdx.x >> 5;
    const int base = (blockIdx.x * 4 + warp) * 2;   // 2 samples per warp
    const int ub = lane * 8;
    const unsigned FULL = 0xffffffffu;

    const int myflag = g_flag[lane];
    const bool fast = __all_sync(FULL, myflag);

    if (!fast) {
        general_path(x, b2, gamma, beta, W1, b1, W2, Ws, bs, out, base, lane);
        return;
    }

    // ---------------- FAST single-pass path ----------------
    float xr[2];
    #pragma unroll
    for (int s = 0; s < 2; ++s) xr[s] = x[(base + s) * NF + lane];

    const float wfv = g_wf[lane];
    float c_own = 0.0f;               // sum_f p_f * mean_v_f for sample (lane&1)

    u64 o2[8];
    #pragma unroll
    for (int i = 0; i < 8; ++i) o2[i] = 0ull;

    #pragma unroll 1
    for (int f = 0; f < NF; ++f) {
        u64 cp2[4], cn2[4], wg2[4];
        const float* pb = g_P + f * 3 * NU + ub;
        LD4U(cp2, pb);
        LD4U(cn2, pb + NU);
        LD4U(wg2, pb + 2 * NU);
        const float wf = __shfl_sync(FULL, wfv, f);

        u64 P[2];      // packed (sum_v, sum_v2) per sample
        u64 rr[8];

        #pragma unroll
        for (int s = 0; s < 2; ++s) {
            const float xf = __shfl_sync(FULL, xr[s], f);
            const u64 xf2 = pk(xf, xf);
            const bool up = (xf > 0.0f);
            u64 a1 = 0ull, a2 = 0ull;
            #pragma unroll
            for (int jp = 0; jp < 4; ++jp) {
                u64 c2 = up ? cp2[jp] : cn2[jp];     // SEL on ALU pipe
                u64 t2 = mul2(xf2, c2);              // t = 0.5*h2  (b2==0)
                u64 z2 = mul2(xf2, wg2[jp]);         // 0.5*gate-z  (bg==0)
                float zl, zh; upk(z2, zl, zh);
                u64 th2 = pk(tanh_a(zl), tanh_a(zh));
                u64 v2 = fma2(t2, th2, t2);          // v = g*h2
                rr[s*4+jp] = v2;
                a1 = add2(a1, v2);
                a2 = fma2(v2, v2, a2);
            }
            float l1, h1, l2, h2;
            upk(a1, l1, h1);
            upk(a2, l2, h2);
            P[s] = pk(l1 + h1, l2 + h2);
        }

        // 2-stream mux butterfly: after it, lane l holds full
        // (sum, sumsq) for sample l&1.
        u64 q0 = shfl64x(P[0], 1), q1 = shfl64x(P[1], 1);
        u64 A = (lane & 1) ? add2(P[1], q1) : add2(P[0], q0);
        A = add2(A, shfl64x(A, 2));
        A = add2(A, shfl64x(A, 4));
        A = add2(A, shfl64x(A, 8));
        A = add2(A, shfl64x(A, 16));

        float S1, S2; upk(A, S1, S2);
        float mv  = S1 * INV_U;
        float var = fmaf(S2, INV_U, -mv * mv);
        float iv  = rsqf_(var + 1e-3f);
        float p_own = wf * iv;
        c_own = fmaf(p_own, mv, c_own);

        #pragma unroll
        for (int s = 0; s < 2; ++s) {
            float ps = __shfl_sync(FULL, p_own, s);   // lane s owns sample s
            u64 p2 = pk(ps, ps);
            #pragma unroll
            for (int jp = 0; jp < 4; ++jp)
                o2[s*4+jp] = fma2(rr[s*4+jp], p2, o2[s*4+jp]);
        }
    }

    #pragma unroll
    for (int s = 0; s < 2; ++s) {
        float cs = __shfl_sync(FULL, c_own, s);
        u64 nc2 = pk(-cs, -cs);
        ulonglong2 v0, v1;
        v0.x = add2(o2[s*4+0], nc2); v0.y = add2(o2[s*4+1], nc2);
        v1.x = add2(o2[s*4+2], nc2); v1.y = add2(o2[s*4+3], nc2);
        ulonglong2* op = (ulonglong2*)(out + (size_t)(base + s) * NU + ub);
        op[0] = v0;
        op[1] = v1;
    }
}

extern "C" void kernel_launch(void* const* d_in, const int* in_sizes, int n_in,
                              void* d_out, int out_size)
{
    const float* x     = (const float*)d_in[0];
    const float* W1    = (const float*)d_in[1];
    const float* b1    = (const float*)d_in[2];
    const float* W2    = (const float*)d_in[3];
    const float* b2    = (const float*)d_in[4];
    const float* Wg    = (const float*)d_in[5];
    const float* bg    = (const float*)d_in[6];
    const float* gamma = (const float*)d_in[7];
    const float* beta  = (const float*)d_in[8];
    const float* Ws    = (const float*)d_in[9];
    const float* bs    = (const float*)d_in[10];
    float* out = (float*)d_out;

    const int NT = in_sizes[0] / NF;      // B*T samples (8192)
    const int blocks = NT / 8;            // 8 samples per 128-thread CTA

    prep1_kernel<<<dim3(NF, PSPLIT), 64>>>(W1, W2);
    prep2_kernel<<<NF, 256>>>(b1, b2, Wg, bg, gamma, beta, bs);
    main_kernel<<<blocks, 128>>>(x, b2, gamma, beta, W1, b1, W2, Ws, bs, out);
}

// round 9
// speedup vs baseline: 1.1058x; 1.1058x over previous
#include <cuda_runtime.h>
#include <cstddef>

#define NF 32
#define NU 256
#define INV_U 0.00390625f
#define PSPLIT 32

typedef unsigned long long u64;

// ---- device scratch (no runtime allocation allowed) ----
__device__ float g_pcp[NF * PSPLIT * NU];   // prep partials
__device__ float g_pcn[NF * PSPLIT * NU];
// fused params: [f][slot][NU], slot0=0.5*Cpos, slot1=0.5*Cneg, slot2=0.5*Wg
__device__ float g_P  [NF * 3 * NU];
__device__ float g_b2h[NF * NU];            // 0.5 * b2   (general path)
__device__ float g_bg2[NF * NU];            // 0.5 * bg   (general path)
__device__ float g_gmean[NF];
__device__ float g_bmean[NF];
__device__ float g_wf[NF];                  // sigmoid(bs) for fast path
__device__ int   g_fb1[NF];                 // b1 row == 0
__device__ int   g_flag[NF];                // b1==0 && b2==0 && bg==0 && gamma==1 && beta==0

// ---- f32x2 packed math (Blackwell FFMA2 path) ----
__device__ __forceinline__ u64 pk(float lo, float hi) {
    u64 r; asm("mov.b64 %0,{%1,%2};" : "=l"(r) : "f"(lo), "f"(hi)); return r;
}
__device__ __forceinline__ void upk(u64 v, float& lo, float& hi) {
    asm("mov.b64 {%0,%1},%2;" : "=f"(lo), "=f"(hi) : "l"(v));
}
__device__ __forceinline__ u64 fma2(u64 a, u64 b, u64 c) {
    u64 d; asm("fma.rn.f32x2 %0,%1,%2,%3;" : "=l"(d) : "l"(a), "l"(b), "l"(c)); return d;
}
__device__ __forceinline__ u64 add2(u64 a, u64 b) {
    u64 d; asm("add.rn.f32x2 %0,%1,%2;" : "=l"(d) : "l"(a), "l"(b)); return d;
}
__device__ __forceinline__ u64 mul2(u64 a, u64 b) {
    u64 d; asm("mul.rn.f32x2 %0,%1,%2;" : "=l"(d) : "l"(a), "l"(b)); return d;
}
__device__ __forceinline__ float tanh_a(float z) {
    float r; asm("tanh.approx.f32 %0,%1;" : "=f"(r) : "f"(z)); return r;
}
__device__ __forceinline__ float rsqf_(float d) {
    float r; asm("rsqrt.approx.f32 %0,%1;" : "=f"(r) : "f"(d)); return r;
}
__device__ __forceinline__ u64 shfl64x(u64 v, int m) {
    return __shfl_xor_sync(0xffffffffu, v, m);
}
// sigmoid(z) = 0.5*tanh(0.5*z) + 0.5   (zh = 0.5*z already)
__device__ __forceinline__ float sig_h(float zh) { return fmaf(0.5f, tanh_a(zh), 0.5f); }

#define LD4U(dst, src) do { \
    ulonglong2 _a = *(const ulonglong2*)((src)); \
    ulonglong2 _b = *(const ulonglong2*)((src) + 4); \
    (dst)[0]=_a.x; (dst)[1]=_a.y; (dst)[2]=_b.x; (dst)[3]=_b.y; } while (0)

// ============================================================
// Prep stage 1: partial ReLU-collapsed dense2 reduction.
// grid (NF, PSPLIT=32) x 64 threads. cp.async issues all 8
// 16B row-chunk copies per thread WITHOUT register pressure
// (ptxas kept serializing register-buffered loads to MLP~2);
// DRAM latency is paid once. Each thread reads back only its
// own smem slots -> no barrier needed.
// ============================================================
__global__ void __launch_bounds__(64) prep1_kernel(
    const float* __restrict__ W1, const float* __restrict__ W2)
{
    __shared__ float4 sbuf[8][64];
    const int f = blockIdx.x;
    const int s = blockIdx.y;
    const int q = threadIdx.x;          // column quad: cols [4q, 4q+4)

    const float* base = W2 + (size_t)f * NU * NU + (size_t)(s * 8) * NU + q * 4;
    #pragma unroll
    for (int i = 0; i < 8; ++i) {
        unsigned sa = (unsigned)__cvta_generic_to_shared(&sbuf[i][q]);
        asm volatile("cp.async.ca.shared.global [%0], [%1], 16;"
                     :: "r"(sa), "l"(base + (size_t)i * NU));
    }
    asm volatile("cp.async.commit_group;");

    // overlap: load W1 while copies are in flight
    const float4 w1a = *(const float4*)(W1 + f * NU + s * 8);
    const float4 w1b = *(const float4*)(W1 + f * NU + s * 8 + 4);
    const float w1[8] = {w1a.x, w1a.y, w1a.z, w1a.w, w1b.x, w1b.y, w1b.z, w1b.w};

    asm volatile("cp.async.wait_group 0;");

    float4 cp = make_float4(0.f, 0.f, 0.f, 0.f);
    float4 cn = make_float4(0.f, 0.f, 0.f, 0.f);
    #pragma unroll
    for (int i = 0; i < 8; ++i) {
        float4 w2 = sbuf[i][q];
        const float wp = fmaxf(w1[i], 0.0f), wn = fminf(w1[i], 0.0f);
        cp.x = fmaf(wp, w2.x, cp.x); cp.y = fmaf(wp, w2.y, cp.y);
        cp.z = fmaf(wp, w2.z, cp.z); cp.w = fmaf(wp, w2.w, cp.w);
        cn.x = fmaf(wn, w2.x, cn.x); cn.y = fmaf(wn, w2.y, cn.y);
        cn.z = fmaf(wn, w2.z, cn.z); cn.w = fmaf(wn, w2.w, cn.w);
    }
    *(float4*)(g_pcp + (f * PSPLIT + s) * NU + q * 4) = cp;
    *(float4*)(g_pcn + (f * PSPLIT + s) * NU + q * 4) = cn;
}

// ============================================================
// Prep stage 2: deterministic partial reduce + fused param
// block + gamma/beta means + flags + fast-path weights.
// ============================================================
__global__ void __launch_bounds__(256) prep2_kernel(
    const float* __restrict__ b1, const float* __restrict__ b2,
    const float* __restrict__ Wg, const float* __restrict__ bg,
    const float* __restrict__ gamma, const float* __restrict__ beta,
    const float* __restrict__ bs)
{
    const int f = blockIdx.x;
    const int v = threadIdx.x;

    __shared__ float red[NU];
    __shared__ int fl_b1, fl_all;
    if (v == 0) { fl_b1 = 1; fl_all = 1; }
    __syncthreads();
    // all writers store 0: race-free
    if (b1[f * NU + v] != 0.0f) { fl_b1 = 0; fl_all = 0; }
    if (b2[f * NU + v] != 0.0f) fl_all = 0;
    if (bg[f * NU + v] != 0.0f) fl_all = 0;
    if (gamma[f * NU + v] != 1.0f) fl_all = 0;
    if (beta[f * NU + v]  != 0.0f) fl_all = 0;

    float cp = 0.0f, cn = 0.0f;
    #pragma unroll 8
    for (int s = 0; s < PSPLIT; ++s) {
        cp += g_pcp[(f * PSPLIT + s) * NU + v];
        cn += g_pcn[(f * PSPLIT + s) * NU + v];
    }
    g_P[f * 3 * NU + v]          = 0.5f * cp;              // slot 0: 0.5*Cpos
    g_P[f * 3 * NU + NU + v]     = 0.5f * cn;              // slot 1: 0.5*Cneg
    g_P[f * 3 * NU + 2 * NU + v] = 0.5f * Wg[f * NU + v];  // slot 2: 0.5*Wg
    g_b2h[f * NU + v] = 0.5f * b2[f * NU + v];
    g_bg2[f * NU + v] = 0.5f * bg[f * NU + v];

    red[v] = gamma[f * NU + v]; __syncthreads();
    for (int s = 128; s > 0; s >>= 1) { if (v < s) red[v] += red[v + s]; __syncthreads(); }
    if (v == 0) g_gmean[f] = red[0] * INV_U;
    __syncthreads();
    red[v] = beta[f * NU + v]; __syncthreads();
    for (int s = 128; s > 0; s >>= 1) { if (v < s) red[v] += red[v + s]; __syncthreads(); }
    if (v == 0) {
        g_bmean[f] = red[0] * INV_U;
        g_fb1[f]  = fl_b1;
        g_flag[f] = fl_all;
        g_wf[f]   = sig_h(0.5f * bs[f]);
    }
}

// Honest O(U) fallback when b1[f,:] is not all-zero (never taken on bench data).
// Produces t[j] = 0.5 * h2[j].
__device__ __noinline__ void slow_t(float xf, int f, int ubase,
                                    const float* __restrict__ W1, const float* __restrict__ b1,
                                    const float* __restrict__ W2, const float* __restrict__ b2,
                                    float* t)
{
    float h2v[8];
    #pragma unroll
    for (int j = 0; j < 8; ++j) h2v[j] = b2[f * NU + ubase + j];
    const float* w1r = W1 + f * NU;
    const float* b1r = b1 + f * NU;
    const float* w2r = W2 + (size_t)f * NU * NU + ubase;
    for (int k = 0; k < NU; ++k) {
        float h1 = fmaxf(fmaf(xf, w1r[k], b1r[k]), 0.0f);
        const float* w2k = w2r + (size_t)k * NU;
        #pragma unroll
        for (int j = 0; j < 8; ++j) h2v[j] = fmaf(h1, w2k[j], h2v[j]);
    }
    #pragma unroll
    for (int j = 0; j < 8; ++j) t[j] = 0.5f * h2v[j];
}

// Compute packed t2[4] (t = 0.5*h2) for one (sample, f).
__device__ __forceinline__ void make_t(int fb1, float xf, u64 xf2, int f, int ub,
                                       const u64* cp2, const u64* cn2, const u64* b2h2,
                                       const float* __restrict__ W1, const float* __restrict__ b1,
                                       const float* __restrict__ W2, const float* __restrict__ b2,
                                       u64* t2)
{
    if (fb1) {
        const bool up = (xf > 0.0f);
        #pragma unroll
        for (int jp = 0; jp < 4; ++jp) {
            u64 c2 = up ? cp2[jp] : cn2[jp];
            t2[jp] = fma2(xf2, c2, b2h2[jp]);
        }
    } else {
        float t[8];
        slow_t(xf, f, ub, W1, b1, W2, b2, t);
        #pragma unroll
        for (int jp = 0; jp < 4; ++jp) t2[jp] = pk(t[2*jp], t[2*jp+1]);
    }
}

// ============================================================
// Main fused kernel (R7 structure). 64-thread CTAs (2 warps,
// 8 samples) -> grid 1024 -> ~6.9 CTAs/SM. Warp owns 4
// samples for ALL f; interleaved packed butterfly reduces all
// 4 samples' (sum, sumsq) in ONE 5-level tree.
//
// Fast path (b1,b2,bg==0; gamma==1; beta==0): single pass on
// v = g*h2 (shift-invariant LN), predicated Cpos/Cneg select
// (ALU pipe), fused param block (one address register).
// ============================================================
__global__ void __launch_bounds__(64, 8) main_kernel(
    const float* __restrict__ x, const float* __restrict__ b2,
    const float* __restrict__ gamma, const float* __restrict__ beta,
    const float* __restrict__ W1, const float* __restrict__ b1,
    const float* __restrict__ W2,
    const float* __restrict__ Ws, const float* __restrict__ bs,
    float* __restrict__ out)
{
    const int lane = threadIdx.x & 31;
    const int warp = threadIdx.x >> 5;
    const int base = (blockIdx.x * 2 + warp) * 4;   // 4 samples per warp
    const int ub = lane * 8;
    const unsigned FULL = 0xffffffffu;

    float xr[4];
    #pragma unroll
    for (int s = 0; s < 4; ++s) xr[s] = x[(base + s) * NF + lane];

    const int myflag = g_flag[lane];
    const bool fast = __all_sync(FULL, myflag);

    u64 o2[16];
    #pragma unroll
    for (int i = 0; i < 16; ++i) o2[i] = 0ull;

    if (fast) {
        // ---------------- FAST single-pass path ----------------
        const float wfv = g_wf[lane];
        float c_own = 0.0f;               // sum_f p_f * mean_v_f for sample lane&3

        #pragma unroll 1
        for (int f = 0; f < NF; ++f) {
            u64 cp2[4], cn2[4], wg2[4];
            const float* pb = g_P + f * 3 * NU + ub;
            LD4U(cp2, pb);
            LD4U(cn2, pb + NU);
            LD4U(wg2, pb + 2 * NU);
            const float wf = __shfl_sync(FULL, wfv, f);

            u64 P[4];      // packed (sum_v, sum_v2) per sample
            u64 rr[16];

            #pragma unroll
            for (int s = 0; s < 4; ++s) {
                const float xf = __shfl_sync(FULL, xr[s], f);
                const u64 xf2 = pk(xf, xf);
                const bool up = (xf > 0.0f);
                u64 a1 = 0ull, a2 = 0ull;
                #pragma unroll
                for (int jp = 0; jp < 4; ++jp) {
                    u64 c2 = up ? cp2[jp] : cn2[jp];     // SEL on ALU pipe
                    u64 t2 = mul2(xf2, c2);              // t = 0.5*h2  (b2==0)
                    u64 z2 = mul2(xf2, wg2[jp]);         // 0.5*gate-z  (bg==0)
                    float zl, zh; upk(z2, zl, zh);
                    u64 th2 = pk(tanh_a(zl), tanh_a(zh));
                    u64 v2 = fma2(t2, th2, t2);          // v = g*h2
                    rr[s*4+jp] = v2;
                    a1 = add2(a1, v2);
                    a2 = fma2(v2, v2, a2);
                }
                float l1, h1, l2, h2;
                upk(a1, l1, h1);
                upk(a2, l2, h2);
                P[s] = pk(l1 + h1, l2 + h2);
            }

            // interleaved packed butterfly: one tree reduces all 4 samples
            u64 t0 = shfl64x(P[0], 1), t1 = shfl64x(P[1], 1);
            u64 A = (lane & 1) ? add2(P[1], t1) : add2(P[0], t0);
            u64 t2_ = shfl64x(P[2], 1), t3 = shfl64x(P[3], 1);
            u64 B = (lane & 1) ? add2(P[3], t3) : add2(P[2], t2_);
            u64 tA = shfl64x(A, 2), tB = shfl64x(B, 2);
            u64 Q = (lane & 2) ? add2(B, tB) : add2(A, tA);
            Q = add2(Q, shfl64x(Q, 4));
            Q = add2(Q, shfl64x(Q, 8));
            Q = add2(Q, shfl64x(Q, 16));
            // lane now holds full (sum, sumsq) for sample lane&3

            float S1, S2; upk(Q, S1, S2);
            float mv  = S1 * INV_U;
            float var = fmaf(S2, INV_U, -mv * mv);
            float iv  = rsqf_(var + 1e-3f);
            float p_own = wf * iv;
            c_own = fmaf(p_own, mv, c_own);

            #pragma unroll
            for (int s = 0; s < 4; ++s) {
                float ps = __shfl_sync(FULL, p_own, s);   // lane s owns sample s
                u64 p2 = pk(ps, ps);
                #pragma unroll
                for (int jp = 0; jp < 4; ++jp)
                    o2[s*4+jp] = fma2(rr[s*4+jp], p2, o2[s*4+jp]);
            }
        }
        #pragma unroll
        for (int s = 0; s < 4; ++s) {
            float cs = __shfl_sync(FULL, c_own, s);
            u64 nc2 = pk(-cs, -cs);
            ulonglong2 v0, v1;
            v0.x = add2(o2[s*4+0], nc2); v0.y = add2(o2[s*4+1], nc2);
            v1.x = add2(o2[s*4+2], nc2); v1.y = add2(o2[s*4+3], nc2);
            ulonglong2* op = (ulonglong2*)(out + (size_t)(base + s) * NU + ub);
            op[0] = v0;
            op[1] = v1;
        }
        return;
    }

    // ---------------- GENERAL two-pass path ----------------
    float mlv[4] = {0,0,0,0}, muv[4] = {0,0,0,0}, ivv[4] = {0,0,0,0};

    #pragma unroll 1
    for (int f = 0; f < NF; ++f) {
        u64 cp2[4], cn2[4], wg2[4], bg2[4], b2h2[4], gm2[4];
        const float* pb = g_P + f * 3 * NU + ub;
        LD4U(cp2, pb);
        LD4U(cn2, pb + NU);
        LD4U(wg2, pb + 2 * NU);
        LD4U(bg2,  g_bg2 + f * NU + ub);
        LD4U(b2h2, g_b2h + f * NU + ub);
        LD4U(gm2,  gamma + f * NU + ub);
        const int fb1 = g_fb1[f];
        const float gmean = g_gmean[f], bmean = g_bmean[f];

        float s1[4], s2[4], s3[4];

        #pragma unroll
        for (int s = 0; s < 4; ++s) {
            const float xf = __shfl_sync(FULL, xr[s], f);
            const u64 xf2 = pk(xf, xf);
            u64 t2[4];
            make_t(fb1, xf, xf2, f, ub, cp2, cn2, b2h2, W1, b1, W2, b2, t2);

            u64 a1 = 0ull, a2 = 0ull, a3 = 0ull;
            #pragma unroll
            for (int jp = 0; jp < 4; ++jp) {
                u64 z2 = fma2(xf2, wg2[jp], bg2[jp]);
                float zl, zh; upk(z2, zl, zh);
                u64 th2 = pk(tanh_a(zl), tanh_a(zh));
                u64 r2 = add2(fma2(t2[jp], th2, t2[jp]), xf2);
                a1 = add2(a1, r2);
                a2 = fma2(r2, r2, a2);
                a3 = fma2(gm2[jp], r2, a3);
            }
            float l, h;
            upk(a1, l, h); s1[s] = l + h;
            upk(a2, l, h); s2[s] = l + h;
            upk(a3, l, h); s3[s] = l + h;
        }
        #pragma unroll
        for (int m = 16; m > 0; m >>= 1) {
            #pragma unroll
            for (int s = 0; s < 4; ++s) {
                s1[s] += __shfl_xor_sync(FULL, s1[s], m);
                s2[s] += __shfl_xor_sync(FULL, s2[s], m);
                s3[s] += __shfl_xor_sync(FULL, s3[s], m);
            }
        }
        #pragma unroll
        for (int s = 0; s < 4; ++s) {
            float mu  = s1[s] * INV_U;
            float var = fmaf(s2[s], INV_U, -mu * mu);
            float iv  = rsqf_(var + 1e-3f);
            float t   = fmaf(-mu, gmean, s3[s] * INV_U);
            float ml  = fmaf(t, iv, bmean);
            bool mine = (lane == f);
            mlv[s] = mine ? ml : mlv[s];
            muv[s] = mine ? mu : muv[s];
            ivv[s] = mine ? iv : ivv[s];
        }
    }

    // selection weights: w[f'=lane] = sigmoid(ml . Ws[:,lane] + bs[lane])
    float wv[4];
    const float bsv = bs[lane];
    #pragma unroll
    for (int s = 0; s < 4; ++s) {
        float z = bsv;
        #pragma unroll
        for (int k = 0; k < NF; ++k)
            z = fmaf(__shfl_sync(FULL, mlv[s], k), Ws[k * NF + lane], z);
        wv[s] = sig_h(0.5f * z);
    }

    // second pass: recompute r, apply LN affine, accumulate output
    #pragma unroll 1
    for (int f = 0; f < NF; ++f) {
        u64 cp2[4], cn2[4], wg2[4], bg2[4], b2h2[4], gm2[4], bt2[4];
        const float* pb = g_P + f * 3 * NU + ub;
        LD4U(cp2, pb);
        LD4U(cn2, pb + NU);
        LD4U(wg2, pb + 2 * NU);
        LD4U(bg2,  g_bg2 + f * NU + ub);
        LD4U(b2h2, g_b2h + f * NU + ub);
        LD4U(gm2,  gamma + f * NU + ub);
        LD4U(bt2,  beta  + f * NU + ub);
        const int fb1 = g_fb1[f];

        #pragma unroll
        for (int s = 0; s < 4; ++s) {
            const float xf = __shfl_sync(FULL, xr[s],  f);
            const float wq = __shfl_sync(FULL, wv[s],  f);
            const float mu = __shfl_sync(FULL, muv[s], f);
            const float iv = __shfl_sync(FULL, ivv[s], f);
            const float p  = wq * iv;
            const u64 xf2  = pk(xf, xf);
            const u64 p2   = pk(p, p);
            const u64 nmu2 = pk(-mu, -mu);
            const u64 wq2  = pk(wq, wq);

            u64 t2[4];
            make_t(fb1, xf, xf2, f, ub, cp2, cn2, b2h2, W1, b1, W2, b2, t2);

            #pragma unroll
            for (int jp = 0; jp < 4; ++jp) {
                u64 z2 = fma2(xf2, wg2[jp], bg2[jp]);
                float zl, zh; upk(z2, zl, zh);
                u64 th2 = pk(tanh_a(zl), tanh_a(zh));
                u64 r2 = add2(fma2(t2[jp], th2, t2[jp]), xf2);
                u64 d2 = mul2(add2(r2, nmu2), gm2[jp]);
                o2[s*4+jp] = fma2(d2, p2, o2[s*4+jp]);
                o2[s*4+jp] = fma2(bt2[jp], wq2, o2[s*4+jp]);
            }
        }
    }

    #pragma unroll
    for (int s = 0; s < 4; ++s) {
        ulonglong2 v0, v1;
        v0.x = o2[s*4+0]; v0.y = o2[s*4+1];
        v1.x = o2[s*4+2]; v1.y = o2[s*4+3];
        ulonglong2* op = (ulonglong2*)(out + (size_t)(base + s) * NU + ub);
        op[0] = v0;
        op[1] = v1;
    }
}

extern "C" void kernel_launch(void* const* d_in, const int* in_sizes, int n_in,
                              void* d_out, int out_size)
{
    const float* x     = (const float*)d_in[0];
    const float* W1    = (const float*)d_in[1];
    const float* b1    = (const float*)d_in[2];
    const float* W2    = (const float*)d_in[3];
    const float* b2    = (const float*)d_in[4];
    const float* Wg    = (const float*)d_in[5];
    const float* bg    = (const float*)d_in[6];
    const float* gamma = (const float*)d_in[7];
    const float* beta  = (const float*)d_in[8];
    const float* Ws    = (const float*)d_in[9];
    const float* bs    = (const float*)d_in[10];
    float* out = (float*)d_out;

    const int NT = in_sizes[0] / NF;      // B*T samples (8192)
    const int blocks = NT / 8;            // 8 samples per 64-thread CTA

    prep1_kernel<<<dim3(NF, PSPLIT), 64>>>(W1, W2);
    prep2_kernel<<<NF, 256>>>(b1, b2, Wg, bg, gamma, beta, bs);
    main_kernel<<<blocks, 64>>>(x, b2, gamma, beta, W1, b1, W2, Ws, bs, out);
}

// round 10
// speedup vs baseline: 1.1548x; 1.0444x over previous
#include <cuda_runtime.h>
#include <cstddef>
#include <cstdint>

#define NF 32
#define NU 256
#define INV_U 0.00390625f
#define PSPLIT 16

typedef unsigned long long u64;

// ---- device scratch (no runtime allocation allowed) ----
__device__ float g_pcp[NF * PSPLIT * NU];   // prep partials
__device__ float g_pcn[NF * PSPLIT * NU];
__device__ float g_CA [NF * NU];            // 0.25*(Cpos+Cneg)
__device__ float g_CD [NF * NU];            // 0.25*(Cpos-Cneg)
__device__ float g_b2h[NF * NU];            // 0.5 * b2
__device__ float g_Wg2[NF * NU];            // 0.5 * Wg
__device__ float g_bg2[NF * NU];            // 0.5 * bg
__device__ float g_gmean[NF];
__device__ float g_bmean[NF];
__device__ float g_wf[NF];                  // sigmoid(bs) for fast path
__device__ int   g_fb1[NF];                 // b1 row == 0
__device__ int   g_flag[NF];                // b1==0 && b2==0 && bg==0 && gamma==1 && beta==0

// ---- f32x2 packed math (Blackwell FFMA2 path) ----
__device__ __forceinline__ u64 pk(float lo, float hi) {
    u64 r; asm("mov.b64 %0,{%1,%2};" : "=l"(r) : "f"(lo), "f"(hi)); return r;
}
__device__ __forceinline__ void upk(u64 v, float& lo, float& hi) {
    asm("mov.b64 {%0,%1},%2;" : "=f"(lo), "=f"(hi) : "l"(v));
}
__device__ __forceinline__ u64 fma2(u64 a, u64 b, u64 c) {
    u64 d; asm("fma.rn.f32x2 %0,%1,%2,%3;" : "=l"(d) : "l"(a), "l"(b), "l"(c)); return d;
}
__device__ __forceinline__ u64 add2(u64 a, u64 b) {
    u64 d; asm("add.rn.f32x2 %0,%1,%2;" : "=l"(d) : "l"(a), "l"(b)); return d;
}
__device__ __forceinline__ u64 mul2(u64 a, u64 b) {
    u64 d; asm("mul.rn.f32x2 %0,%1,%2;" : "=l"(d) : "l"(a), "l"(b)); return d;
}
__device__ __forceinline__ float tanh_a(float z) {
    float r; asm("tanh.approx.f32 %0,%1;" : "=f"(r) : "f"(z)); return r;
}
__device__ __forceinline__ float rsqf_(float d) {
    float r; asm("rsqrt.approx.f32 %0,%1;" : "=f"(r) : "f"(d)); return r;
}
__device__ __forceinline__ u64 shfl64x(u64 v, int m) {
    return __shfl_xor_sync(0xffffffffu, v, m);
}
// sigmoid(z) = 0.5*tanh(0.5*z) + 0.5   (zh = 0.5*z already)
__device__ __forceinline__ float sig_h(float zh) { return fmaf(0.5f, tanh_a(zh), 0.5f); }

#define LD4U(dst, src) do { \
    ulonglong2 _a = *(const ulonglong2*)((src)); \
    ulonglong2 _b = *(const ulonglong2*)((src) + 4); \
    (dst)[0]=_a.x; (dst)[1]=_a.y; (dst)[2]=_b.x; (dst)[3]=_b.y; } while (0)

#define MBAR_WAIT_P0(mb) do {                                            \
    asm volatile(                                                        \
        "{\n\t.reg .pred P;\n"                                           \
        "W%=:\n\t"                                                       \
        "mbarrier.try_wait.parity.acquire.cta.shared::cta.b64 P, [%0], 0, 0x989680;\n\t" \
        "@!P bra W%=;\n\t}"                                              \
        :: "r"(mb) : "memory"); } while (0)

// ============================================================
// Prep stage 1: partial ReLU-collapsed dense2 reduction.
// grid (NF, PSPLIT=16) x 64 threads. Each CTA's 16 W2 rows are
// one CONTIGUOUS 16KB block -> a single cp.async.bulk (TMA)
// per CTA replaces 8+ per-thread loads (the LSU-issue floor
// that pinned prep1 at ~6us across R5-R9). All 512 CTAs are
// resident in one wave, so the whole 8MB is in flight at once.
// ============================================================
__global__ void __launch_bounds__(64) prep1_kernel(
    const float* __restrict__ W1, const float* __restrict__ W2)
{
    __shared__ alignas(128) float sbuf[16 * NU];   // 16KB
    __shared__ alignas(8) u64 mbar;
    const int f = blockIdx.x;
    const int s = blockIdx.y;
    const int q = threadIdx.x;          // column quad: cols [4q, 4q+4)

    const uint32_t mb = (uint32_t)__cvta_generic_to_shared(&mbar);
    if (q == 0) {
        asm volatile("mbarrier.init.shared.b64 [%0], 1;" :: "r"(mb));
        asm volatile("fence.proxy.async.shared::cta;" ::: "memory");
    }
    __syncthreads();
    if (q == 0) {
        asm volatile("mbarrier.arrive.expect_tx.shared.b64 _, [%0], %1;"
                     :: "r"(mb), "r"(16u * NU * 4u) : "memory");
        const uint32_t sd = (uint32_t)__cvta_generic_to_shared(sbuf);
        const float* src = W2 + (size_t)f * NU * NU + (size_t)(s * 16) * NU;
        asm volatile(
            "cp.async.bulk.shared::cta.global.mbarrier::complete_tx::bytes [%0], [%1], %2, [%3];"
            :: "r"(sd), "l"(src), "r"(16u * NU * 4u), "r"(mb) : "memory");
    }

    // load W1 chunk while the bulk copy is in flight
    const float4 w1a = *(const float4*)(W1 + f * NU + s * 16);
    const float4 w1b = *(const float4*)(W1 + f * NU + s * 16 + 4);
    const float4 w1c = *(const float4*)(W1 + f * NU + s * 16 + 8);
    const float4 w1d = *(const float4*)(W1 + f * NU + s * 16 + 12);
    const float w1[16] = {w1a.x, w1a.y, w1a.z, w1a.w, w1b.x, w1b.y, w1b.z, w1b.w,
                          w1c.x, w1c.y, w1c.z, w1c.w, w1d.x, w1d.y, w1d.z, w1d.w};

    MBAR_WAIT_P0(mb);

    float4 cp = make_float4(0.f, 0.f, 0.f, 0.f);
    float4 cn = make_float4(0.f, 0.f, 0.f, 0.f);
    #pragma unroll
    for (int i = 0; i < 16; ++i) {
        float4 w2 = *(const float4*)(sbuf + i * NU + q * 4);   // conflict-free LDS.128
        const float wp = fmaxf(w1[i], 0.0f), wn = fminf(w1[i], 0.0f);
        cp.x = fmaf(wp, w2.x, cp.x); cp.y = fmaf(wp, w2.y, cp.y);
        cp.z = fmaf(wp, w2.z, cp.z); cp.w = fmaf(wp, w2.w, cp.w);
        cn.x = fmaf(wn, w2.x, cn.x); cn.y = fmaf(wn, w2.y, cn.y);
        cn.z = fmaf(wn, w2.z, cn.z); cn.w = fmaf(wn, w2.w, cn.w);
    }
    *(float4*)(g_pcp + (f * PSPLIT + s) * NU + q * 4) = cp;
    *(float4*)(g_pcn + (f * PSPLIT + s) * NU + q * 4) = cn;
}

// ============================================================
// Prep stage 2: deterministic partial reduce + A/D param form +
// gamma/beta means + flags + fast-path weights.
// ============================================================
__global__ void __launch_bounds__(256) prep2_kernel(
    const float* __restrict__ b1, const float* __restrict__ b2,
    const float* __restrict__ Wg, const float* __restrict__ bg,
    const float* __restrict__ gamma, const float* __restrict__ beta,
    const float* __restrict__ bs)
{
    const int f = blockIdx.x;
    const int v = threadIdx.x;

    __shared__ float red[NU];
    __shared__ int fl_b1, fl_all;
    if (v == 0) { fl_b1 = 1; fl_all = 1; }
    __syncthreads();
    // all writers store 0: race-free
    if (b1[f * NU + v] != 0.0f) { fl_b1 = 0; fl_all = 0; }
    if (b2[f * NU + v] != 0.0f) fl_all = 0;
    if (bg[f * NU + v] != 0.0f) fl_all = 0;
    if (gamma[f * NU + v] != 1.0f) fl_all = 0;
    if (beta[f * NU + v]  != 0.0f) fl_all = 0;

    float cp = 0.0f, cn = 0.0f;
    #pragma unroll 8
    for (int s = 0; s < PSPLIT; ++s) {
        cp += g_pcp[(f * PSPLIT + s) * NU + v];
        cn += g_pcn[(f * PSPLIT + s) * NU + v];
    }
    // t = 0.5*h2 = xf*A + |xf|*D + 0.5*b2
    g_CA [f * NU + v] = 0.25f * (cp + cn);
    g_CD [f * NU + v] = 0.25f * (cp - cn);
    g_b2h[f * NU + v] = 0.5f * b2[f * NU + v];
    g_Wg2[f * NU + v] = 0.5f * Wg[f * NU + v];
    g_bg2[f * NU + v] = 0.5f * bg[f * NU + v];

    red[v] = gamma[f * NU + v]; __syncthreads();
    for (int s = 128; s > 0; s >>= 1) { if (v < s) red[v] += red[v + s]; __syncthreads(); }
    if (v == 0) g_gmean[f] = red[0] * INV_U;
    __syncthreads();
    red[v] = beta[f * NU + v]; __syncthreads();
    for (int s = 128; s > 0; s >>= 1) { if (v < s) red[v] += red[v + s]; __syncthreads(); }
    if (v == 0) {
        g_bmean[f] = red[0] * INV_U;
        g_fb1[f]  = fl_b1;
        g_flag[f] = fl_all;
        g_wf[f]   = sig_h(0.5f * bs[f]);
    }
}

// Honest O(U) fallback when b1[f,:] is not all-zero (never taken on bench data).
// Produces t[j] = 0.5 * h2[j].
__device__ __noinline__ void slow_t(float xf, int f, int ubase,
                                    const float* __restrict__ W1, const float* __restrict__ b1,
                                    const float* __restrict__ W2, const float* __restrict__ b2,
                                    float* t)
{
    float h2v[8];
    #pragma unroll
    for (int j = 0; j < 8; ++j) h2v[j] = b2[f * NU + ubase + j];
    const float* w1r = W1 + f * NU;
    const float* b1r = b1 + f * NU;
    const float* w2r = W2 + (size_t)f * NU * NU + ubase;
    for (int k = 0; k < NU; ++k) {
        float h1 = fmaxf(fmaf(xf, w1r[k], b1r[k]), 0.0f);
        const float* w2k = w2r + (size_t)k * NU;
        #pragma unroll
        for (int j = 0; j < 8; ++j) h2v[j] = fmaf(h1, w2k[j], h2v[j]);
    }
    #pragma unroll
    for (int j = 0; j < 8; ++j) t[j] = 0.5f * h2v[j];
}

// Compute packed t2[4] (t = 0.5*h2) for one (sample, f): t = xf*A + |xf|*D + b2h.
__device__ __forceinline__ void make_t(int fb1, float xf, u64 xf2, u64 axf2, int f, int ub,
                                       const u64* ca2, const u64* cd2, const u64* b2h2,
                                       const float* __restrict__ W1, const float* __restrict__ b1,
                                       const float* __restrict__ W2, const float* __restrict__ b2,
                                       u64* t2)
{
    if (fb1) {
        #pragma unroll
        for (int jp = 0; jp < 4; ++jp)
            t2[jp] = fma2(axf2, cd2[jp], fma2(xf2, ca2[jp], b2h2[jp]));
    } else {
        float t[8];
        slow_t(xf, f, ub, W1, b1, W2, b2, t);
        #pragma unroll
        for (int jp = 0; jp < 4; ++jp) t2[jp] = pk(t[2*jp], t[2*jp+1]);
    }
}

// ============================================================
// Main fused kernel (best-measured structure). 64-thread CTAs
// (2 warps, 8 samples) -> grid 1024. Warp owns 4 samples for
// ALL f; interleaved packed butterfly reduces all 4 samples'
// (sum, sumsq) in ONE 5-level tree.
//
// Fast path (b1,b2,bg==0; gamma==1; beta==0): single pass on
// v = g*h2 (shift-invariant LN), t = xf*A + |xf|*D.
// ============================================================
__global__ void __launch_bounds__(64, 8) main_kernel(
    const float* __restrict__ x, const float* __restrict__ b2,
    const float* __restrict__ gamma, const float* __restrict__ beta,
    const float* __restrict__ W1, const float* __restrict__ b1,
    const float* __restrict__ W2,
    const float* __restrict__ Ws, const float* __restrict__ bs,
    float* __restrict__ out)
{
    const int lane = threadIdx.x & 31;
    const int warp = threadIdx.x >> 5;
    const int base = (blockIdx.x * 2 + warp) * 4;   // 4 samples per warp
    const int ub = lane * 8;
    const unsigned FULL = 0xffffffffu;

    float xr[4];
    #pragma unroll
    for (int s = 0; s < 4; ++s) xr[s] = x[(base + s) * NF + lane];

    const int myflag = g_flag[lane];
    const bool fast = __all_sync(FULL, myflag);

    u64 o2[16];
    #pragma unroll
    for (int i = 0; i < 16; ++i) o2[i] = 0ull;

    if (fast) {
        // ---------------- FAST single-pass path ----------------
        const float wfv = g_wf[lane];
        float c_own = 0.0f;               // sum_f p_f * mean_v_f for sample lane&3

        #pragma unroll 1
        for (int f = 0; f < NF; ++f) {
            u64 wg2[4], ca2[4], cd2[4];
            LD4U(wg2, g_Wg2 + f * NU + ub);
            LD4U(ca2, g_CA  + f * NU + ub);
            LD4U(cd2, g_CD  + f * NU + ub);
            const float wf = __shfl_sync(FULL, wfv, f);

            u64 P[4];      // packed (sum_v, sum_v2) per sample
            u64 rr[16];

            #pragma unroll
            for (int s = 0; s < 4; ++s) {
                const float xf = __shfl_sync(FULL, xr[s], f);
                const float axf = fabsf(xf);
                const u64 xf2  = pk(xf, xf);
                const u64 axf2 = pk(axf, axf);
                u64 a1 = 0ull, a2 = 0ull;
                #pragma unroll
                for (int jp = 0; jp < 4; ++jp) {
                    u64 t2 = fma2(axf2, cd2[jp], mul2(xf2, ca2[jp]));  // t = 0.5*h2
                    u64 z2 = mul2(xf2, wg2[jp]);                       // 0.5*gate-z
                    float zl, zh; upk(z2, zl, zh);
                    u64 th2 = pk(tanh_a(zl), tanh_a(zh));
                    u64 v2 = fma2(t2, th2, t2);                        // v = g*h2
                    rr[s*4+jp] = v2;
                    a1 = add2(a1, v2);
                    a2 = fma2(v2, v2, a2);
                }
                float l1, h1, l2, h2;
                upk(a1, l1, h1);
                upk(a2, l2, h2);
                P[s] = pk(l1 + h1, l2 + h2);
            }

            // interleaved packed butterfly: one tree reduces all 4 samples
            u64 t0 = shfl64x(P[0], 1), t1 = shfl64x(P[1], 1);
            u64 A = (lane & 1) ? add2(P[1], t1) : add2(P[0], t0);
            u64 t2_ = shfl64x(P[2], 1), t3 = shfl64x(P[3], 1);
            u64 B = (lane & 1) ? add2(P[3], t3) : add2(P[2], t2_);
            u64 tA = shfl64x(A, 2), tB = shfl64x(B, 2);
            u64 Q = (lane & 2) ? add2(B, tB) : add2(A, tA);
            Q = add2(Q, shfl64x(Q, 4));
            Q = add2(Q, shfl64x(Q, 8));
            Q = add2(Q, shfl64x(Q, 16));
            // lane now holds full (sum, sumsq) for sample lane&3

            float S1, S2; upk(Q, S1, S2);
            float mv  = S1 * INV_U;
            float var = fmaf(S2, INV_U, -mv * mv);
            float iv  = rsqf_(var + 1e-3f);
            float p_own = wf * iv;
            c_own = fmaf(p_own, mv, c_own);

            #pragma unroll
            for (int s = 0; s < 4; ++s) {
                float ps = __shfl_sync(FULL, p_own, s);   // lane s owns sample s
                u64 p2 = pk(ps, ps);
                #pragma unroll
                for (int jp = 0; jp < 4; ++jp)
                    o2[s*4+jp] = fma2(rr[s*4+jp], p2, o2[s*4+jp]);
            }
        }
        #pragma unroll
        for (int s = 0; s < 4; ++s) {
            float cs = __shfl_sync(FULL, c_own, s);
            u64 nc2 = pk(-cs, -cs);
            ulonglong2 v0, v1;
            v0.x = add2(o2[s*4+0], nc2); v0.y = add2(o2[s*4+1], nc2);
            v1.x = add2(o2[s*4+2], nc2); v1.y = add2(o2[s*4+3], nc2);
            ulonglong2* op = (ulonglong2*)(out + (size_t)(base + s) * NU + ub);
            op[0] = v0;
            op[1] = v1;
        }
        return;
    }

    // ---------------- GENERAL two-pass path ----------------
    float mlv[4] = {0,0,0,0}, muv[4] = {0,0,0,0}, ivv[4] = {0,0,0,0};

    #pragma unroll 1
    for (int f = 0; f < NF; ++f) {
        u64 wg2[4], bg2[4], ca2[4], cd2[4], b2h2[4], gm2[4];
        LD4U(wg2,  g_Wg2 + f * NU + ub);
        LD4U(bg2,  g_bg2 + f * NU + ub);
        LD4U(ca2,  g_CA  + f * NU + ub);
        LD4U(cd2,  g_CD  + f * NU + ub);
        LD4U(b2h2, g_b2h + f * NU + ub);
        LD4U(gm2,  gamma + f * NU + ub);
        const int fb1 = g_fb1[f];
        const float gmean = g_gmean[f], bmean = g_bmean[f];

        float s1[4], s2[4], s3[4];

        #pragma unroll
        for (int s = 0; s < 4; ++s) {
            const float xf = __shfl_sync(FULL, xr[s], f);
            const float axf = fabsf(xf);
            const u64 xf2  = pk(xf, xf);
            const u64 axf2 = pk(axf, axf);
            u64 t2[4];
            make_t(fb1, xf, xf2, axf2, f, ub, ca2, cd2, b2h2, W1, b1, W2, b2, t2);

            u64 a1 = 0ull, a2 = 0ull, a3 = 0ull;
            #pragma unroll
            for (int jp = 0; jp < 4; ++jp) {
                u64 z2 = fma2(xf2, wg2[jp], bg2[jp]);
                float zl, zh; upk(z2, zl, zh);
                u64 th2 = pk(tanh_a(zl), tanh_a(zh));
                u64 r2 = add2(fma2(t2[jp], th2, t2[jp]), xf2);
                a1 = add2(a1, r2);
                a2 = fma2(r2, r2, a2);
                a3 = fma2(gm2[jp], r2, a3);
            }
            float l, h;
            upk(a1, l, h); s1[s] = l + h;
            upk(a2, l, h); s2[s] = l + h;
            upk(a3, l, h); s3[s] = l + h;
        }
        #pragma unroll
        for (int m = 16; m > 0; m >>= 1) {
            #pragma unroll
            for (int s = 0; s < 4; ++s) {
                s1[s] += __shfl_xor_sync(FULL, s1[s], m);
                s2[s] += __shfl_xor_sync(FULL, s2[s], m);
                s3[s] += __shfl_xor_sync(FULL, s3[s], m);
            }
        }
        #pragma unroll
        for (int s = 0; s < 4; ++s) {
            float mu  = s1[s] * INV_U;
            float var = fmaf(s2[s], INV_U, -mu * mu);
            float iv  = rsqf_(var + 1e-3f);
            float t   = fmaf(-mu, gmean, s3[s] * INV_U);
            float ml  = fmaf(t, iv, bmean);
            bool mine = (lane == f);
            mlv[s] = mine ? ml : mlv[s];
            muv[s] = mine ? mu : muv[s];
            ivv[s] = mine ? iv : ivv[s];
        }
    }

    // selection weights: w[f'=lane] = sigmoid(ml . Ws[:,lane] + bs[lane])
    float wv[4];
    const float bsv = bs[lane];
    #pragma unroll
    for (int s = 0; s < 4; ++s) {
        float z = bsv;
        #pragma unroll
        for (int k = 0; k < NF; ++k)
            z = fmaf(__shfl_sync(FULL, mlv[s], k), Ws[k * NF + lane], z);
        wv[s] = sig_h(0.5f * z);
    }

    // second pass: recompute r, apply LN affine, accumulate output
    #pragma unroll 1
    for (int f = 0; f < NF; ++f) {
        u64 wg2[4], bg2[4], ca2[4], cd2[4], b2h2[4], gm2[4], bt2[4];
        LD4U(wg2,  g_Wg2 + f * NU + ub);
        LD4U(bg2,  g_bg2 + f * NU + ub);
        LD4U(ca2,  g_CA  + f * NU + ub);
        LD4U(cd2,  g_CD  + f * NU + ub);
        LD4U(b2h2, g_b2h + f * NU + ub);
        LD4U(gm2,  gamma + f * NU + ub);
        LD4U(bt2,  beta  + f * NU + ub);
        const int fb1 = g_fb1[f];

        #pragma unroll
        for (int s = 0; s < 4; ++s) {
            const float xf = __shfl_sync(FULL, xr[s],  f);
            const float wq = __shfl_sync(FULL, wv[s],  f);
            const float mu = __shfl_sync(FULL, muv[s], f);
            const float iv = __shfl_sync(FULL, ivv[s], f);
            const float p  = wq * iv;
            const float axf = fabsf(xf);
            const u64 xf2  = pk(xf, xf);
            const u64 axf2 = pk(axf, axf);
            const u64 p2   = pk(p, p);
            const u64 nmu2 = pk(-mu, -mu);
            const u64 wq2  = pk(wq, wq);

            u64 t2[4];
            make_t(fb1, xf, xf2, axf2, f, ub, ca2, cd2, b2h2, W1, b1, W2, b2, t2);

            #pragma unroll
            for (int jp = 0; jp < 4; ++jp) {
                u64 z2 = fma2(xf2, wg2[jp], bg2[jp]);
                float zl, zh; upk(z2, zl, zh);
                u64 th2 = pk(tanh_a(zl), tanh_a(zh));
                u64 r2 = add2(fma2(t2[jp], th2, t2[jp]), xf2);
                u64 d2 = mul2(add2(r2, nmu2), gm2[jp]);
                o2[s*4+jp] = fma2(d2, p2, o2[s*4+jp]);
                o2[s*4+jp] = fma2(bt2[jp], wq2, o2[s*4+jp]);
            }
        }
    }

    #pragma unroll
    for (int s = 0; s < 4; ++s) {
        ulonglong2 v0, v1;
        v0.x = o2[s*4+0]; v0.y = o2[s*4+1];
        v1.x = o2[s*4+2]; v1.y = o2[s*4+3];
        ulonglong2* op = (ulonglong2*)(out + (size_t)(base + s) * NU + ub);
        op[0] = v0;
        op[1] = v1;
    }
}

extern "C" void kernel_launch(void* const* d_in, const int* in_sizes, int n_in,
                              void* d_out, int out_size)
{
    const float* x     = (const float*)d_in[0];
    const float* W1    = (const float*)d_in[1];
    const float* b1    = (const float*)d_in[2];
    const float* W2    = (const float*)d_in[3];
    const float* b2    = (const float*)d_in[4];
    const float* Wg    = (const float*)d_in[5];
    const float* bg    = (const float*)d_in[6];
    const float* gamma = (const float*)d_in[7];
    const float* beta  = (const float*)d_in[8];
    const float* Ws    = (const float*)d_in[9];
    const float* bs    = (const float*)d_in[10];
    float* out = (float*)d_out;

    const int NT = in_sizes[0] / NF;      // B*T samples (8192)
    const int blocks = NT / 8;            // 8 samples per 64-thread CTA

    prep1_kernel<<<dim3(NF, PSPLIT), 64>>>(W1, W2);
    prep2_kernel<<<NF, 256>>>(b1, b2, Wg, bg, gamma, beta, bs);
    main_kernel<<<blocks, 64>>>(x, b2, gamma, beta, W1, b1, W2, Ws, bs, out);
}

// round 11
// speedup vs baseline: 1.2044x; 1.0429x over previous
#include <cuda_runtime.h>
#include <cstddef>
#include <cstdint>

#define NF 32
#define NU 256
#define INV_U 0.00390625f
#define PSPLIT 4

typedef unsigned long long u64;

// ---- device scratch (no runtime allocation allowed) ----
__device__ float g_pcp[NF * PSPLIT * NU];   // prep partials
__device__ float g_pcn[NF * PSPLIT * NU];
__device__ float g_CA [NF * NU];            // 0.25*(Cpos+Cneg)
__device__ float g_CD [NF * NU];            // 0.25*(Cpos-Cneg)
__device__ float g_b2h[NF * NU];            // 0.5 * b2
__device__ float g_Wg2[NF * NU];            // 0.5 * Wg
__device__ float g_bg2[NF * NU];            // 0.5 * bg
__device__ float g_gmean[NF];
__device__ float g_bmean[NF];
__device__ float g_wf[NF];                  // sigmoid(bs) for fast path
__device__ int   g_fb1[NF];                 // b1 row == 0
__device__ int   g_flag[NF];                // b1==0 && b2==0 && bg==0 && gamma==1 && beta==0

// ---- f32x2 packed math (Blackwell FFMA2 path) ----
__device__ __forceinline__ u64 pk(float lo, float hi) {
    u64 r; asm("mov.b64 %0,{%1,%2};" : "=l"(r) : "f"(lo), "f"(hi)); return r;
}
__device__ __forceinline__ void upk(u64 v, float& lo, float& hi) {
    asm("mov.b64 {%0,%1},%2;" : "=f"(lo), "=f"(hi) : "l"(v));
}
__device__ __forceinline__ u64 fma2(u64 a, u64 b, u64 c) {
    u64 d; asm("fma.rn.f32x2 %0,%1,%2,%3;" : "=l"(d) : "l"(a), "l"(b), "l"(c)); return d;
}
__device__ __forceinline__ u64 add2(u64 a, u64 b) {
    u64 d; asm("add.rn.f32x2 %0,%1,%2;" : "=l"(d) : "l"(a), "l"(b)); return d;
}
__device__ __forceinline__ u64 mul2(u64 a, u64 b) {
    u64 d; asm("mul.rn.f32x2 %0,%1,%2;" : "=l"(d) : "l"(a), "l"(b)); return d;
}
__device__ __forceinline__ float tanh_a(float z) {
    float r; asm("tanh.approx.f32 %0,%1;" : "=f"(r) : "f"(z)); return r;
}
__device__ __forceinline__ float rsqf_(float d) {
    float r; asm("rsqrt.approx.f32 %0,%1;" : "=f"(r) : "f"(d)); return r;
}
__device__ __forceinline__ u64 shfl64x(u64 v, int m) {
    return __shfl_xor_sync(0xffffffffu, v, m);
}
// sigmoid(z) = 0.5*tanh(0.5*z) + 0.5   (zh = 0.5*z already)
__device__ __forceinline__ float sig_h(float zh) { return fmaf(0.5f, tanh_a(zh), 0.5f); }

#define LD4U(dst, src) do { \
    ulonglong2 _a = *(const ulonglong2*)((src)); \
    ulonglong2 _b = *(const ulonglong2*)((src) + 4); \
    (dst)[0]=_a.x; (dst)[1]=_a.y; (dst)[2]=_b.x; (dst)[3]=_b.y; } while (0)

#define MBAR_WAIT(mb, ph) do {                                           \
    asm volatile(                                                        \
        "{\n\t.reg .pred P;\n"                                           \
        "W%=:\n\t"                                                       \
        "mbarrier.try_wait.parity.acquire.cta.shared::cta.b64 P, [%0], %1, 0x989680;\n\t" \
        "@!P bra W%=;\n\t}"                                              \
        :: "r"(mb), "r"(ph) : "memory"); } while (0)

// ============================================================
// Prep stage 1: partial ReLU-collapsed dense2 reduction.
// grid (NF, 4) x 256 threads. Each CTA owns a 64-row quarter
// of one f = 4 x 16KB chunks streamed through a 2-stage
// double-buffered TMA ring (R10's single-bulk version just sat
// in the mbarrier wait: latency, not issue, was the binder).
// 128 CTAs keep ~4MB in flight -> DRAM-BW bound.
// ============================================================
__global__ void __launch_bounds__(256) prep1_kernel(
    const float* __restrict__ W1, const float* __restrict__ W2)
{
    __shared__ alignas(128) float sbuf[2][16 * NU];   // 2 x 16KB
    __shared__ alignas(8) u64 mbar[2];
    __shared__ float4 rcp[4][64], rcn[4][64];
    __shared__ float w1s[64];

    const int f  = blockIdx.x;
    const int s4 = blockIdx.y;            // row quarter [s4*64, s4*64+64)
    const int v  = threadIdx.x;
    const int q  = v & 63;                // column quad: cols [4q, 4q+4)
    const int rg = v >> 6;                // row group within chunk

    const uint32_t mb0 = (uint32_t)__cvta_generic_to_shared(&mbar[0]);
    const uint32_t sb0 = (uint32_t)__cvta_generic_to_shared(&sbuf[0][0]);
    const float* w2src = W2 + (size_t)f * NU * NU + (size_t)(s4 * 64) * NU;

#define TMA_ISSUE(st, chunk) do {                                        \
    uint32_t _mb = mb0 + (uint32_t)(st) * 8u;                            \
    asm volatile("mbarrier.arrive.expect_tx.shared.b64 _, [%0], %1;"     \
                 :: "r"(_mb), "r"(16384u) : "memory");                   \
    uint32_t _sd = sb0 + (uint32_t)(st) * 16384u;                        \
    asm volatile("cp.async.bulk.shared::cta.global.mbarrier::complete_tx::bytes [%0], [%1], %2, [%3];" \
                 :: "r"(_sd), "l"(w2src + (size_t)(chunk) * 16 * NU),    \
                    "r"(16384u), "r"(_mb) : "memory");                   \
} while (0)

    if (v == 0) {
        asm volatile("mbarrier.init.shared.b64 [%0], 1;" :: "r"(mb0));
        asm volatile("mbarrier.init.shared.b64 [%0], 1;" :: "r"(mb0 + 8));
        asm volatile("fence.proxy.async.shared::cta;" ::: "memory");
    }
    if (v < 64) w1s[v] = W1[f * NU + s4 * 64 + v];
    __syncthreads();
    if (v == 0) { TMA_ISSUE(0, 0); TMA_ISSUE(1, 1); }

    float4 cp = make_float4(0.f, 0.f, 0.f, 0.f);
    float4 cn = make_float4(0.f, 0.f, 0.f, 0.f);

    #pragma unroll
    for (int c = 0; c < 4; ++c) {
        const int st = c & 1;
        MBAR_WAIT(mb0 + st * 8, (c >> 1) & 1);
        const float* sb = &sbuf[st][0];
        #pragma unroll
        for (int i = 0; i < 4; ++i) {
            const int row = rg * 4 + i;
            const float w1 = w1s[c * 16 + row];
            const float wp = fmaxf(w1, 0.0f), wn = fminf(w1, 0.0f);
            float4 w2 = *(const float4*)(sb + row * NU + q * 4);
            cp.x = fmaf(wp, w2.x, cp.x); cp.y = fmaf(wp, w2.y, cp.y);
            cp.z = fmaf(wp, w2.z, cp.z); cp.w = fmaf(wp, w2.w, cp.w);
            cn.x = fmaf(wn, w2.x, cn.x); cn.y = fmaf(wn, w2.y, cn.y);
            cn.z = fmaf(wn, w2.z, cn.z); cn.w = fmaf(wn, w2.w, cn.w);
        }
        __syncthreads();
        if (v == 0 && c + 2 < 4) TMA_ISSUE(st, c + 2);
    }
#undef TMA_ISSUE

    rcp[rg][q] = cp;
    rcn[rg][q] = cn;
    __syncthreads();
    if (rg == 0) {
        float4 a = rcp[0][q], b = rcn[0][q];
        #pragma unroll
        for (int g = 1; g < 4; ++g) {
            float4 pa = rcp[g][q], pb = rcn[g][q];
            a.x += pa.x; a.y += pa.y; a.z += pa.z; a.w += pa.w;
            b.x += pb.x; b.y += pb.y; b.z += pb.z; b.w += pb.w;
        }
        *(float4*)(g_pcp + (f * PSPLIT + s4) * NU + q * 4) = a;
        *(float4*)(g_pcn + (f * PSPLIT + s4) * NU + q * 4) = b;
    }
}

// ============================================================
// Prep stage 2: deterministic partial reduce + A/D param form +
// gamma/beta means + flags + fast-path weights.
// ============================================================
__global__ void __launch_bounds__(256) prep2_kernel(
    const float* __restrict__ b1, const float* __restrict__ b2,
    const float* __restrict__ Wg, const float* __restrict__ bg,
    const float* __restrict__ gamma, const float* __restrict__ beta,
    const float* __restrict__ bs)
{
    const int f = blockIdx.x;
    const int v = threadIdx.x;

    __shared__ float red[NU];
    __shared__ int fl_b1, fl_all;
    if (v == 0) { fl_b1 = 1; fl_all = 1; }
    __syncthreads();
    // all writers store 0: race-free
    if (b1[f * NU + v] != 0.0f) { fl_b1 = 0; fl_all = 0; }
    if (b2[f * NU + v] != 0.0f) fl_all = 0;
    if (bg[f * NU + v] != 0.0f) fl_all = 0;
    if (gamma[f * NU + v] != 1.0f) fl_all = 0;
    if (beta[f * NU + v]  != 0.0f) fl_all = 0;

    float cp = 0.0f, cn = 0.0f;
    #pragma unroll
    for (int s = 0; s < PSPLIT; ++s) {
        cp += g_pcp[(f * PSPLIT + s) * NU + v];
        cn += g_pcn[(f * PSPLIT + s) * NU + v];
    }
    // t = 0.5*h2 = xf*A + |xf|*D + 0.5*b2
    g_CA [f * NU + v] = 0.25f * (cp + cn);
    g_CD [f * NU + v] = 0.25f * (cp - cn);
    g_b2h[f * NU + v] = 0.5f * b2[f * NU + v];
    g_Wg2[f * NU + v] = 0.5f * Wg[f * NU + v];
    g_bg2[f * NU + v] = 0.5f * bg[f * NU + v];

    red[v] = gamma[f * NU + v]; __syncthreads();
    for (int s = 128; s > 0; s >>= 1) { if (v < s) red[v] += red[v + s]; __syncthreads(); }
    if (v == 0) g_gmean[f] = red[0] * INV_U;
    __syncthreads();
    red[v] = beta[f * NU + v]; __syncthreads();
    for (int s = 128; s > 0; s >>= 1) { if (v < s) red[v] += red[v + s]; __syncthreads(); }
    if (v == 0) {
        g_bmean[f] = red[0] * INV_U;
        g_fb1[f]  = fl_b1;
        g_flag[f] = fl_all;
        g_wf[f]   = sig_h(0.5f * bs[f]);
    }
}

// Honest O(U) fallback when b1[f,:] is not all-zero (never taken on bench data).
// Produces t[j] = 0.5 * h2[j].
__device__ __noinline__ void slow_t(float xf, int f, int ubase,
                                    const float* __restrict__ W1, const float* __restrict__ b1,
                                    const float* __restrict__ W2, const float* __restrict__ b2,
                                    float* t)
{
    float h2v[8];
    #pragma unroll
    for (int j = 0; j < 8; ++j) h2v[j] = b2[f * NU + ubase + j];
    const float* w1r = W1 + f * NU;
    const float* b1r = b1 + f * NU;
    const float* w2r = W2 + (size_t)f * NU * NU + ubase;
    for (int k = 0; k < NU; ++k) {
        float h1 = fmaxf(fmaf(xf, w1r[k], b1r[k]), 0.0f);
        const float* w2k = w2r + (size_t)k * NU;
        #pragma unroll
        for (int j = 0; j < 8; ++j) h2v[j] = fmaf(h1, w2k[j], h2v[j]);
    }
    #pragma unroll
    for (int j = 0; j < 8; ++j) t[j] = 0.5f * h2v[j];
}

// Compute packed t2[4] (t = 0.5*h2) for one (sample, f): t = xf*A + |xf|*D + b2h.
__device__ __forceinline__ void make_t(int fb1, float xf, u64 xf2, u64 axf2, int f, int ub,
                                       const u64* ca2, const u64* cd2, const u64* b2h2,
                                       const float* __restrict__ W1, const float* __restrict__ b1,
                                       const float* __restrict__ W2, const float* __restrict__ b2,
                                       u64* t2)
{
    if (fb1) {
        #pragma unroll
        for (int jp = 0; jp < 4; ++jp)
            t2[jp] = fma2(axf2, cd2[jp], fma2(xf2, ca2[jp], b2h2[jp]));
    } else {
        float t[8];
        slow_t(xf, f, ub, W1, b1, W2, b2, t);
        #pragma unroll
        for (int jp = 0; jp < 4; ++jp) t2[jp] = pk(t[2*jp], t[2*jp+1]);
    }
}

// ============================================================
// Main fused kernel (best-measured structure, UNCHANGED).
// 64-thread CTAs (2 warps, 8 samples) -> grid 1024. Warp owns
// 4 samples for ALL f; interleaved packed butterfly reduces
// all 4 samples' (sum, sumsq) in ONE 5-level tree.
//
// Fast path (b1,b2,bg==0; gamma==1; beta==0): single pass on
// v = g*h2 (shift-invariant LN), t = xf*A + |xf|*D.
// ============================================================
__global__ void __launch_bounds__(64, 8) main_kernel(
    const float* __restrict__ x, const float* __restrict__ b2,
    const float* __restrict__ gamma, const float* __restrict__ beta,
    const float* __restrict__ W1, const float* __restrict__ b1,
    const float* __restrict__ W2,
    const float* __restrict__ Ws, const float* __restrict__ bs,
    float* __restrict__ out)
{
    const int lane = threadIdx.x & 31;
    const int warp = threadIdx.x >> 5;
    const int base = (blockIdx.x * 2 + warp) * 4;   // 4 samples per warp
    const int ub = lane * 8;
    const unsigned FULL = 0xffffffffu;

    float xr[4];
    #pragma unroll
    for (int s = 0; s < 4; ++s) xr[s] = x[(base + s) * NF + lane];

    const int myflag = g_flag[lane];
    const bool fast = __all_sync(FULL, myflag);

    u64 o2[16];
    #pragma unroll
    for (int i = 0; i < 16; ++i) o2[i] = 0ull;

    if (fast) {
        // ---------------- FAST single-pass path ----------------
        const float wfv = g_wf[lane];
        float c_own = 0.0f;               // sum_f p_f * mean_v_f for sample lane&3

        #pragma unroll 1
        for (int f = 0; f < NF; ++f) {
            u64 wg2[4], ca2[4], cd2[4];
            LD4U(wg2, g_Wg2 + f * NU + ub);
            LD4U(ca2, g_CA  + f * NU + ub);
            LD4U(cd2, g_CD  + f * NU + ub);
            const float wf = __shfl_sync(FULL, wfv, f);

            u64 P[4];      // packed (sum_v, sum_v2) per sample
            u64 rr[16];

            #pragma unroll
            for (int s = 0; s < 4; ++s) {
                const float xf = __shfl_sync(FULL, xr[s], f);
                const float axf = fabsf(xf);
                const u64 xf2  = pk(xf, xf);
                const u64 axf2 = pk(axf, axf);
                u64 a1 = 0ull, a2 = 0ull;
                #pragma unroll
                for (int jp = 0; jp < 4; ++jp) {
                    u64 t2 = fma2(axf2, cd2[jp], mul2(xf2, ca2[jp]));  // t = 0.5*h2
                    u64 z2 = mul2(xf2, wg2[jp]);                       // 0.5*gate-z
                    float zl, zh; upk(z2, zl, zh);
                    u64 th2 = pk(tanh_a(zl), tanh_a(zh));
                    u64 v2 = fma2(t2, th2, t2);                        // v = g*h2
                    rr[s*4+jp] = v2;
                    a1 = add2(a1, v2);
                    a2 = fma2(v2, v2, a2);
                }
                float l1, h1, l2, h2;
                upk(a1, l1, h1);
                upk(a2, l2, h2);
                P[s] = pk(l1 + h1, l2 + h2);
            }

            // interleaved packed butterfly: one tree reduces all 4 samples
            u64 t0 = shfl64x(P[0], 1), t1 = shfl64x(P[1], 1);
            u64 A = (lane & 1) ? add2(P[1], t1) : add2(P[0], t0);
            u64 t2_ = shfl64x(P[2], 1), t3 = shfl64x(P[3], 1);
            u64 B = (lane & 1) ? add2(P[3], t3) : add2(P[2], t2_);
            u64 tA = shfl64x(A, 2), tB = shfl64x(B, 2);
            u64 Q = (lane & 2) ? add2(B, tB) : add2(A, tA);
            Q = add2(Q, shfl64x(Q, 4));
            Q = add2(Q, shfl64x(Q, 8));
            Q = add2(Q, shfl64x(Q, 16));
            // lane now holds full (sum, sumsq) for sample lane&3

            float S1, S2; upk(Q, S1, S2);
            float mv  = S1 * INV_U;
            float var = fmaf(S2, INV_U, -mv * mv);
            float iv  = rsqf_(var + 1e-3f);
            float p_own = wf * iv;
            c_own = fmaf(p_own, mv, c_own);

            #pragma unroll
            for (int s = 0; s < 4; ++s) {
                float ps = __shfl_sync(FULL, p_own, s);   // lane s owns sample s
                u64 p2 = pk(ps, ps);
                #pragma unroll
                for (int jp = 0; jp < 4; ++jp)
                    o2[s*4+jp] = fma2(rr[s*4+jp], p2, o2[s*4+jp]);
            }
        }
        #pragma unroll
        for (int s = 0; s < 4; ++s) {
            float cs = __shfl_sync(FULL, c_own, s);
            u64 nc2 = pk(-cs, -cs);
            ulonglong2 v0, v1;
            v0.x = add2(o2[s*4+0], nc2); v0.y = add2(o2[s*4+1], nc2);
            v1.x = add2(o2[s*4+2], nc2); v1.y = add2(o2[s*4+3], nc2);
            ulonglong2* op = (ulonglong2*)(out + (size_t)(base + s) * NU + ub);
            op[0] = v0;
            op[1] = v1;
        }
        return;
    }

    // ---------------- GENERAL two-pass path ----------------
    float mlv[4] = {0,0,0,0}, muv[4] = {0,0,0,0}, ivv[4] = {0,0,0,0};

    #pragma unroll 1
    for (int f = 0; f < NF; ++f) {
        u64 wg2[4], bg2[4], ca2[4], cd2[4], b2h2[4], gm2[4];
        LD4U(wg2,  g_Wg2 + f * NU + ub);
        LD4U(bg2,  g_bg2 + f * NU + ub);
        LD4U(ca2,  g_CA  + f * NU + ub);
        LD4U(cd2,  g_CD  + f * NU + ub);
        LD4U(b2h2, g_b2h + f * NU + ub);
        LD4U(gm2,  gamma + f * NU + ub);
        const int fb1 = g_fb1[f];
        const float gmean = g_gmean[f], bmean = g_bmean[f];

        float s1[4], s2[4], s3[4];

        #pragma unroll
        for (int s = 0; s < 4; ++s) {
            const float xf = __shfl_sync(FULL, xr[s], f);
            const float axf = fabsf(xf);
            const u64 xf2  = pk(xf, xf);
            const u64 axf2 = pk(axf, axf);
            u64 t2[4];
            make_t(fb1, xf, xf2, axf2, f, ub, ca2, cd2, b2h2, W1, b1, W2, b2, t2);

            u64 a1 = 0ull, a2 = 0ull, a3 = 0ull;
            #pragma unroll
            for (int jp = 0; jp < 4; ++jp) {
                u64 z2 = fma2(xf2, wg2[jp], bg2[jp]);
                float zl, zh; upk(z2, zl, zh);
                u64 th2 = pk(tanh_a(zl), tanh_a(zh));
                u64 r2 = add2(fma2(t2[jp], th2, t2[jp]), xf2);
                a1 = add2(a1, r2);
                a2 = fma2(r2, r2, a2);
                a3 = fma2(gm2[jp], r2, a3);
            }
            float l, h;
            upk(a1, l, h); s1[s] = l + h;
            upk(a2, l, h); s2[s] = l + h;
            upk(a3, l, h); s3[s] = l + h;
        }
        #pragma unroll
        for (int m = 16; m > 0; m >>= 1) {
            #pragma unroll
            for (int s = 0; s < 4; ++s) {
                s1[s] += __shfl_xor_sync(FULL, s1[s], m);
                s2[s] += __shfl_xor_sync(FULL, s2[s], m);
                s3[s] += __shfl_xor_sync(FULL, s3[s], m);
            }
        }
        #pragma unroll
        for (int s = 0; s < 4; ++s) {
            float mu  = s1[s] * INV_U;
            float var = fmaf(s2[s], INV_U, -mu * mu);
            float iv  = rsqf_(var + 1e-3f);
            float t   = fmaf(-mu, gmean, s3[s] * INV_U);
            float ml  = fmaf(t, iv, bmean);
            bool mine = (lane == f);
            mlv[s] = mine ? ml : mlv[s];
            muv[s] = mine ? mu : muv[s];
            ivv[s] = mine ? iv : ivv[s];
        }
    }

    // selection weights: w[f'=lane] = sigmoid(ml . Ws[:,lane] + bs[lane])
    float wv[4];
    const float bsv = bs[lane];
    #pragma unroll
    for (int s = 0; s < 4; ++s) {
        float z = bsv;
        #pragma unroll
        for (int k = 0; k < NF; ++k)
            z = fmaf(__shfl_sync(FULL, mlv[s], k), Ws[k * NF + lane], z);
        wv[s] = sig_h(0.5f * z);
    }

    // second pass: recompute r, apply LN affine, accumulate output
    #pragma unroll 1
    for (int f = 0; f < NF; ++f) {
        u64 wg2[4], bg2[4], ca2[4], cd2[4], b2h2[4], gm2[4], bt2[4];
        LD4U(wg2,  g_Wg2 + f * NU + ub);
        LD4U(bg2,  g_bg2 + f * NU + ub);
        LD4U(ca2,  g_CA  + f * NU + ub);
        LD4U(cd2,  g_CD  + f * NU + ub);
        LD4U(b2h2, g_b2h + f * NU + ub);
        LD4U(gm2,  gamma + f * NU + ub);
        LD4U(bt2,  beta  + f * NU + ub);
        const int fb1 = g_fb1[f];

        #pragma unroll
        for (int s = 0; s < 4; ++s) {
            const float xf = __shfl_sync(FULL, xr[s],  f);
            const float wq = __shfl_sync(FULL, wv[s],  f);
            const float mu = __shfl_sync(FULL, muv[s], f);
            const float iv = __shfl_sync(FULL, ivv[s], f);
            const float p  = wq * iv;
            const float axf = fabsf(xf);
            const u64 xf2  = pk(xf, xf);
            const u64 axf2 = pk(axf, axf);
            const u64 p2   = pk(p, p);
            const u64 nmu2 = pk(-mu, -mu);
            const u64 wq2  = pk(wq, wq);

            u64 t2[4];
            make_t(fb1, xf, xf2, axf2, f, ub, ca2, cd2, b2h2, W1, b1, W2, b2, t2);

            #pragma unroll
            for (int jp = 0; jp < 4; ++jp) {
                u64 z2 = fma2(xf2, wg2[jp], bg2[jp]);
                float zl, zh; upk(z2, zl, zh);
                u64 th2 = pk(tanh_a(zl), tanh_a(zh));
                u64 r2 = add2(fma2(t2[jp], th2, t2[jp]), xf2);
                u64 d2 = mul2(add2(r2, nmu2), gm2[jp]);
                o2[s*4+jp] = fma2(d2, p2, o2[s*4+jp]);
                o2[s*4+jp] = fma2(bt2[jp], wq2, o2[s*4+jp]);
            }
        }
    }

    #pragma unroll
    for (int s = 0; s < 4; ++s) {
        ulonglong2 v0, v1;
        v0.x = o2[s*4+0]; v0.y = o2[s*4+1];
        v1.x = o2[s*4+2]; v1.y = o2[s*4+3];
        ulonglong2* op = (ulonglong2*)(out + (size_t)(base + s) * NU + ub);
        op[0] = v0;
        op[1] = v1;
    }
}

extern "C" void kernel_launch(void* const* d_in, const int* in_sizes, int n_in,
                              void* d_out, int out_size)
{
    const float* x     = (const float*)d_in[0];
    const float* W1    = (const float*)d_in[1];
    const float* b1    = (const float*)d_in[2];
    const float* W2    = (const float*)d_in[3];
    const float* b2    = (const float*)d_in[4];
    const float* Wg    = (const float*)d_in[5];
    const float* bg    = (const float*)d_in[6];
    const float* gamma = (const float*)d_in[7];
    const float* beta  = (const float*)d_in[8];
    const float* Ws    = (const float*)d_in[9];
    const float* bs    = (const float*)d_in[10];
    float* out = (float*)d_out;

    const int NT = in_sizes[0] / NF;      // B*T samples (8192)
    const int blocks = NT / 8;            // 8 samples per 64-thread CTA

    prep1_kernel<<<dim3(NF, PSPLIT), 256>>>(W1, W2);
    prep2_kernel<<<NF, 256>>>(b1, b2, Wg, bg, gamma, beta, bs);
    main_kernel<<<blocks, 64>>>(x, b2, gamma, beta, W1, b1, W2, Ws, bs, out);
}